// round 1
// baseline (speedup 1.0000x reference)
#include <cuda_runtime.h>
#include <math.h>

#define B_ 16
#define N_ 196
#define C_ 512
#define T_ 20
#define D_ 128
#define S_ 38
#define MM_ 38416            // 196*196
#define QSIZE 8028160        // B*D*T*N
#define INV_TEMP (1.0f/0.07f)
#define EPS_ 1e-20f

// ---------------- scratch (static device globals; no allocation) ----------------
__device__ float g_qA[B_*T_*N_*D_];              // [b][t][n][d] normalized q, 32MB
__device__ float g_P[(size_t)B_*S_*MM_];         // [b][s][n][m] transition mats, 93MB
__device__ float g_buf1[(size_t)B_*19*MM_];      // tree ping
__device__ float g_buf2[(size_t)B_*10*MM_];      // tree pong (final At in [b][0])
__device__ float g_partial[2*B_];                // per-b loss-sum / acc-sum

// =============================================================================
// Kernel A: spatial pool + linear head + L2 normalize.
// One CTA per bn (3136 CTAs, 128 threads). Input maps[bn] is 512x20 float4s:
// the (h,w)=4 pooled elements are exactly one float4 -> fully coalesced stream.
// GEMM: thread owns 4 consecutive d x 5 t (20 accums); W chunked through smem.
// =============================================================================
#define SMEM_A_BYTES ((C_*T_ + 64*D_ + 32) * sizeof(float))

__global__ __launch_bounds__(128) void kA(const float* __restrict__ maps,
                                          const float* __restrict__ W,
                                          const float* __restrict__ bias,
                                          float* __restrict__ qout) {
  extern __shared__ float sm[];
  float* qp    = sm;                 // [c][t] pooled, 10240 floats; later reused as y[t][d]
  float* Ws    = sm + C_*T_;         // 64x128 W chunk; later reused as reduction area
  float* inorm = Ws + 64*D_;         // 20 inverse norms

  const int bn  = blockIdx.x;
  const int tid = threadIdx.x;

  // ---- stage 1: pool (coalesced float4 stream) ----
  const float4* src = reinterpret_cast<const float4*>(maps) + (size_t)bn * (C_*T_);
  for (int i = tid; i < C_*T_; i += 128) {
    float4 v = src[i];
    qp[i] = (v.x + v.y + v.z + v.w) * 0.25f;
  }
  __syncthreads();

  // ---- stage 2: y[d][t] = b[d] + sum_c qp[c][t] * W[c][d] ----
  const int d0 = (tid & 31) * 4;      // 4 consecutive d
  const int t0 = (tid >> 5) * 5;      // 5 consecutive t
  float acc[4][5];
#pragma unroll
  for (int a = 0; a < 4; ++a)
#pragma unroll
    for (int t = 0; t < 5; ++t) acc[a][t] = 0.f;

  for (int cc = 0; cc < C_; cc += 64) {
    __syncthreads();
    const float4* wg  = reinterpret_cast<const float4*>(W + (size_t)cc * D_);
    float4*       ws4 = reinterpret_cast<float4*>(Ws);
    for (int j = tid; j < 64*D_/4; j += 128) ws4[j] = wg[j];
    __syncthreads();
#pragma unroll 4
    for (int k = 0; k < 64; ++k) {
      const int c = cc + k;
      float4 w = *reinterpret_cast<const float4*>(&Ws[k*D_ + d0]);
      float qv[5];
#pragma unroll
      for (int t = 0; t < 5; ++t) qv[t] = qp[c*T_ + t0 + t];
#pragma unroll
      for (int t = 0; t < 5; ++t) {
        acc[0][t] += w.x * qv[t];
        acc[1][t] += w.y * qv[t];
        acc[2][t] += w.z * qv[t];
        acc[3][t] += w.w * qv[t];
      }
    }
  }
  __syncthreads();   // all qp/Ws reads done; safe to repurpose both regions

  float4 bv4 = *reinterpret_cast<const float4*>(bias + d0);
  float bvv[4] = {bv4.x, bv4.y, bv4.z, bv4.w};

  // write y into qp as [t][d] and accumulate per-thread sumsq partials
  float part[5];
#pragma unroll
  for (int t = 0; t < 5; ++t) {
    float p = 0.f;
#pragma unroll
    for (int dd = 0; dd < 4; ++dd) {
      float yv = acc[dd][t] + bvv[dd];
      qp[(t0 + t)*D_ + (d0 + dd)] = yv;
      p += yv * yv;
    }
    part[t] = p;
  }
  float* red = Ws;   // 20 x 32 partials
#pragma unroll
  for (int t = 0; t < 5; ++t) red[(t0 + t)*32 + (tid & 31)] = part[t];
  __syncthreads();

  if (tid < T_) {
    float ss = 0.f;
#pragma unroll
    for (int j = 0; j < 32; ++j) ss += red[tid*32 + j];
    inorm[tid] = 1.0f / fmaxf(sqrtf(ss), 1e-12f);
  }
  __syncthreads();

  const int b = bn / N_;
  const int n = bn % N_;
  for (int i = tid; i < T_*D_; i += 128) {
    const int t = i >> 7, d = i & 127;
    float v = qp[t*D_ + d] * inorm[t];
    g_qA[((size_t)(b*T_ + t)*N_ + n)*D_ + d] = v;                 // coalesced in d
    qout[((size_t)(b*D_ + d)*T_ + t)*N_ + n] = v;                 // output layout (B,d,T,N)
  }
}

// =============================================================================
// Kernel B: affinity + palindrome softmax. One CTA per (b,t), t in [0,19).
// Computes A = Q_t Q_{t+1}^T / tau (196x196, K=128) in smem; then
//   P[t]    = row-softmax(A)          (forward)
//   P[37-t] = per-column softmax of A written transposed  (backward)
// 392 threads = 28x14, thread tile 7x14, K chunked by 16.
// =============================================================================
#define SMEM_B_BYTES ((N_*197 + 2*16*N_) * sizeof(float))

__global__ __launch_bounds__(392) void kB() {
  extern __shared__ float sm[];
  float* Sm = sm;                    // 196 x 197 (padded)
  float* Qa = sm + N_*197;           // 16 x 196
  float* Qb = Qa + 16*N_;            // 16 x 196

  const int t   = blockIdx.x;
  const int b   = blockIdx.y;
  const int tid = threadIdx.x;
  const int ty  = tid / 14, tx = tid % 14;   // 28 x 14
  const int r0  = ty * 7,   c0 = tx * 14;

  const float* qa_base = g_qA + (size_t)((b*T_ + t    )*N_) * D_;
  const float* qb_base = g_qA + (size_t)((b*T_ + t + 1)*N_) * D_;

  float acc[7][14];
#pragma unroll
  for (int i = 0; i < 7; ++i)
#pragma unroll
    for (int j = 0; j < 14; ++j) acc[i][j] = 0.f;

  for (int k0 = 0; k0 < D_; k0 += 16) {
    __syncthreads();
    for (int idx = tid; idx < N_*16; idx += 392) {
      const int n = idx >> 4, k = idx & 15;
      Qa[k*N_ + n] = qa_base[(size_t)n*D_ + k0 + k];
      Qb[k*N_ + n] = qb_base[(size_t)n*D_ + k0 + k];
    }
    __syncthreads();
#pragma unroll
    for (int k = 0; k < 16; ++k) {
      float ra[7], rb[14];
#pragma unroll
      for (int i = 0; i < 7; ++i)  ra[i] = Qa[k*N_ + r0 + i];
#pragma unroll
      for (int j = 0; j < 14; ++j) rb[j] = Qb[k*N_ + c0 + j];
#pragma unroll
      for (int i = 0; i < 7; ++i)
#pragma unroll
        for (int j = 0; j < 14; ++j) acc[i][j] += ra[i] * rb[j];
    }
  }
  __syncthreads();

#pragma unroll
  for (int i = 0; i < 7; ++i)
#pragma unroll
    for (int j = 0; j < 14; ++j)
      Sm[(r0 + i)*197 + (c0 + j)] = acc[i][j] * INV_TEMP;
  __syncthreads();

  // exp in place (values bounded |x| <= 1/0.07, no max-shift needed in fp32)
  for (int idx = tid; idx < N_*N_; idx += 392) {
    const int rr = idx / N_, mm = idx - rr*N_;
    Sm[rr*197 + mm] = __expf(Sm[rr*197 + mm]);
  }
  __syncthreads();

  float* rinv = Qa;         // reuse
  float* cinv = Qa + N_;
  if (tid < N_) {
    float rs = 0.f, cs = 0.f;
    for (int m = 0; m < N_; ++m) {
      rs += Sm[tid*197 + m];
      cs += Sm[m*197 + tid];
    }
    rinv[tid] = 1.0f / rs;
    cinv[tid] = 1.0f / cs;
  }
  __syncthreads();

  float* Pf = g_P + (size_t)(b*S_ + t       )*MM_;
  float* Pb = g_P + (size_t)(b*S_ + (37 - t))*MM_;
  for (int idx = tid; idx < N_*N_; idx += 392) {
    const int rr = idx / N_, mm = idx - rr*N_;
    Pf[idx] = Sm[rr*197 + mm] * rinv[rr];   // forward: row softmax
    Pb[idx] = Sm[mm*197 + rr] * cinv[rr];   // backward: P[n][m] = e(A[m][n])/colsum[n]
  }
}

// =============================================================================
// Kernel C: product-tree level. C = src[2p+1] @ src[2p] (196x196x196 fp32).
// Grid (2 row-tiles, npairs[+carry], 16 b); 196 threads = 14x14, tile 98x196,
// thread tile 7x14, K chunked by 14. Carry block copies the odd matrix through.
// Output staged through padded smem for coalesced stores.
// =============================================================================
#define SMEM_C_BYTES ((14*98 + 14*N_ + 98*197) * sizeof(float))

__global__ __launch_bounds__(196) void kC(int level, int Lin, int Lout, int npairs) {
  extern __shared__ float sm[];
  float* As = sm;                 // [k][n] 14x98
  float* Bs = sm + 14*98;         // [k][m] 14x196
  float* Sm = Bs + 14*N_;         // 98x197 staging

  const float* src; float* dst;
  switch (level) {
    case 0:  src = g_P;    dst = g_buf1; break;
    case 1:  src = g_buf1; dst = g_buf2; break;
    case 2:  src = g_buf2; dst = g_buf1; break;
    case 3:  src = g_buf1; dst = g_buf2; break;
    case 4:  src = g_buf2; dst = g_buf1; break;
    default: src = g_buf1; dst = g_buf2; break;
  }

  const int tile = blockIdx.x;
  const int p    = blockIdx.y;
  const int b    = blockIdx.z;
  const int tid  = threadIdx.x;

  if (p >= npairs) {    // carry: copy last src matrix to dst[npairs]
    const float* Sg = src + ((size_t)b*Lin + (Lin - 1))*MM_;
    float*       Dg = dst + ((size_t)b*Lout + npairs)*MM_;
    const int start = tile * (MM_/2);
    for (int i = start + tid; i < start + MM_/2; i += 196) Dg[i] = Sg[i];
    return;
  }

  const float* Am = src + ((size_t)b*Lin + 2*p + 1)*MM_;
  const float* Bm = src + ((size_t)b*Lin + 2*p    )*MM_;
  float*       Cm = dst + ((size_t)b*Lout + p     )*MM_;

  const int row0 = tile * 98;
  const int ty = tid / 14, tx = tid % 14;
  const int r0 = ty * 7,   c0 = tx * 14;

  float acc[7][14];
#pragma unroll
  for (int i = 0; i < 7; ++i)
#pragma unroll
    for (int j = 0; j < 14; ++j) acc[i][j] = 0.f;

  for (int k0 = 0; k0 < N_; k0 += 14) {
    __syncthreads();
    for (int idx = tid; idx < 98*14; idx += 196) {
      const int n = idx / 14, k = idx - n*14;
      As[k*98 + n] = Am[(size_t)(row0 + n)*N_ + k0 + k];
    }
#pragma unroll
    for (int kk = 0; kk < 14; ++kk)
      Bs[kk*N_ + tid] = Bm[(size_t)(k0 + kk)*N_ + tid];
    __syncthreads();
#pragma unroll
    for (int k = 0; k < 14; ++k) {
      float ra[7], rb[14];
#pragma unroll
      for (int i = 0; i < 7; ++i)  ra[i] = As[k*98 + r0 + i];
#pragma unroll
      for (int j = 0; j < 14; ++j) rb[j] = Bs[k*N_ + c0 + j];
#pragma unroll
      for (int i = 0; i < 7; ++i)
#pragma unroll
        for (int j = 0; j < 14; ++j) acc[i][j] += ra[i] * rb[j];
    }
  }
  __syncthreads();
#pragma unroll
  for (int i = 0; i < 7; ++i)
#pragma unroll
    for (int j = 0; j < 14; ++j)
      Sm[(r0 + i)*197 + (c0 + j)] = acc[i][j];
  __syncthreads();
  for (int idx = tid; idx < 98*N_; idx += 196) {
    const int rr = idx / N_;                       // column == tid (coalesced)
    Cm[(size_t)(row0 + rr)*N_ + tid] = Sm[rr*197 + tid];
  }
}

// =============================================================================
// Kernel D: per-row loss/acc from final At (g_buf2, one matrix per b).
// logsumexp(log(x+eps)) == log(rowsum + N*eps); argmax(log(x+eps)) == argmax(x).
// =============================================================================
__global__ void kD() {
  __shared__ float sl[N_], sa[N_];
  const int b = blockIdx.x, n = threadIdx.x;
  const float* row = g_buf2 + (size_t)b*MM_ + (size_t)n*N_;
  float rs = 0.f, best = -1.f;
  int bi = 0;
  for (int m = 0; m < N_; ++m) {
    const float v = row[m];
    rs += v;
    if (v > best) { best = v; bi = m; }
  }
  const float diag = row[n];
  sl[n] = logf(rs + (float)N_ * EPS_) - logf(diag + EPS_);
  sa[n] = (bi == n) ? 1.f : 0.f;
  __syncthreads();
  if (n == 0) {
    float L = 0.f, A = 0.f;
    for (int i = 0; i < N_; ++i) { L += sl[i]; A += sa[i]; }
    g_partial[b]      = L;
    g_partial[B_ + b] = A;
  }
}

__global__ void kE(float* out, int out_size) {
  float L = 0.f, A = 0.f;
  for (int b = 0; b < B_; ++b) { L += g_partial[b]; A += g_partial[B_ + b]; }
  const float inv = 1.0f / (float)(B_ * N_);
  if (out_size > QSIZE)     out[QSIZE]     = L * inv;
  if (out_size > QSIZE + 1) out[QSIZE + 1] = A * inv;
}

// =============================================================================
extern "C" void kernel_launch(void* const* d_in, const int* in_sizes, int n_in,
                              void* d_out, int out_size) {
  const float* maps = (const float*)d_in[0];
  const float* W    = (const float*)d_in[1];
  const float* bias = (const float*)d_in[2];
  float* out = (float*)d_out;

  cudaFuncSetAttribute(kA, cudaFuncAttributeMaxDynamicSharedMemorySize, (int)SMEM_A_BYTES);
  cudaFuncSetAttribute(kB, cudaFuncAttributeMaxDynamicSharedMemorySize, (int)SMEM_B_BYTES);
  cudaFuncSetAttribute(kC, cudaFuncAttributeMaxDynamicSharedMemorySize, (int)SMEM_C_BYTES);

  kA<<<B_*N_, 128, SMEM_A_BYTES>>>(maps, W, bias, out);
  kB<<<dim3(T_ - 1, B_), 392, SMEM_B_BYTES>>>();

  // product tree: 38 -> 19 -> 10 -> 5 -> 3 -> 2 -> 1  (order-preserving pairing)
  // {level, Lin, Lout, npairs, carry}
  const int lv[6][5] = {
    {0, 38, 19, 19, 0},
    {1, 19, 10,  9, 1},
    {2, 10,  5,  5, 0},
    {3,  5,  3,  2, 1},
    {4,  3,  2,  1, 1},
    {5,  2,  1,  1, 0},
  };
  for (int l = 0; l < 6; ++l) {
    kC<<<dim3(2, lv[l][3] + lv[l][4], B_), 196, SMEM_C_BYTES>>>(
        lv[l][0], lv[l][1], lv[l][2], lv[l][3]);
  }

  kD<<<B_, N_>>>();
  kE<<<1, 1>>>(out, out_size);
}

// round 2
// speedup vs baseline: 1.2147x; 1.2147x over previous
#include <cuda_runtime.h>
#include <math.h>

#define B_ 16
#define N_ 196
#define C_ 512
#define T_ 20
#define D_ 128
#define S_ 38
#define NP_ 224                    // padded column stride for chain matrices
#define MMP_ (N_*NP_)              // 43904 floats per padded matrix
#define QSIZE 8028160              // B*D*T*N
#define INV_TEMP (1.0f/0.07f)
#define EPS_ 1e-20f

// ---------------- scratch (static device globals; no allocation) ----------------
__device__ float g_qA[B_*T_*N_*D_];                  // [b][t][n][d] normalized q
__device__ float g_P[(size_t)B_*S_*MMP_];            // padded transition mats
__device__ float g_buf1[(size_t)B_*19*MMP_];         // tree ping
__device__ float g_buf2[(size_t)B_*10*MMP_];         // tree pong (final At at [b][0])
__device__ float g_partial[2*B_];

// =============================================================================
// Kernel A: spatial pool + linear head + L2 normalize. (unchanged from R1)
// =============================================================================
#define SMEM_A_BYTES ((C_*T_ + 64*D_ + 32) * sizeof(float))

__global__ __launch_bounds__(128) void kA(const float* __restrict__ maps,
                                          const float* __restrict__ W,
                                          const float* __restrict__ bias,
                                          float* __restrict__ qout) {
  extern __shared__ float sm[];
  float* qp    = sm;
  float* Ws    = sm + C_*T_;
  float* inorm = Ws + 64*D_;

  const int bn  = blockIdx.x;
  const int tid = threadIdx.x;

  const float4* src = reinterpret_cast<const float4*>(maps) + (size_t)bn * (C_*T_);
  for (int i = tid; i < C_*T_; i += 128) {
    float4 v = src[i];
    qp[i] = (v.x + v.y + v.z + v.w) * 0.25f;
  }
  __syncthreads();

  const int d0 = (tid & 31) * 4;
  const int t0 = (tid >> 5) * 5;
  float acc[4][5];
#pragma unroll
  for (int a = 0; a < 4; ++a)
#pragma unroll
    for (int t = 0; t < 5; ++t) acc[a][t] = 0.f;

  for (int cc = 0; cc < C_; cc += 64) {
    __syncthreads();
    const float4* wg  = reinterpret_cast<const float4*>(W + (size_t)cc * D_);
    float4*       ws4 = reinterpret_cast<float4*>(Ws);
    for (int j = tid; j < 64*D_/4; j += 128) ws4[j] = wg[j];
    __syncthreads();
#pragma unroll 4
    for (int k = 0; k < 64; ++k) {
      const int c = cc + k;
      float4 w = *reinterpret_cast<const float4*>(&Ws[k*D_ + d0]);
      float qv[5];
#pragma unroll
      for (int t = 0; t < 5; ++t) qv[t] = qp[c*T_ + t0 + t];
#pragma unroll
      for (int t = 0; t < 5; ++t) {
        acc[0][t] += w.x * qv[t];
        acc[1][t] += w.y * qv[t];
        acc[2][t] += w.z * qv[t];
        acc[3][t] += w.w * qv[t];
      }
    }
  }
  __syncthreads();

  float4 bv4 = *reinterpret_cast<const float4*>(bias + d0);
  float bvv[4] = {bv4.x, bv4.y, bv4.z, bv4.w};

  float part[5];
#pragma unroll
  for (int t = 0; t < 5; ++t) {
    float p = 0.f;
#pragma unroll
    for (int dd = 0; dd < 4; ++dd) {
      float yv = acc[dd][t] + bvv[dd];
      qp[(t0 + t)*D_ + (d0 + dd)] = yv;
      p += yv * yv;
    }
    part[t] = p;
  }
  float* red = Ws;
#pragma unroll
  for (int t = 0; t < 5; ++t) red[(t0 + t)*32 + (tid & 31)] = part[t];
  __syncthreads();

  if (tid < T_) {
    float ss = 0.f;
#pragma unroll
    for (int j = 0; j < 32; ++j) ss += red[tid*32 + j];
    inorm[tid] = 1.0f / fmaxf(sqrtf(ss), 1e-12f);
  }
  __syncthreads();

  const int b = bn / N_;
  const int n = bn % N_;
  for (int i = tid; i < T_*D_; i += 128) {
    const int t = i >> 7, d = i & 127;
    float v = qp[t*D_ + d] * inorm[t];
    g_qA[((size_t)(b*T_ + t)*N_ + n)*D_ + d] = v;
    qout[((size_t)(b*D_ + d)*T_ + t)*N_ + n] = v;
  }
}

// =============================================================================
// Kernel B: affinity + palindrome softmax -> padded P (stride 224, pad zeroed).
// =============================================================================
#define SMEM_B_BYTES ((N_*197 + 2*16*N_) * sizeof(float))

__global__ __launch_bounds__(392) void kB() {
  extern __shared__ float sm[];
  float* Sm = sm;                    // 196 x 197
  float* Qa = sm + N_*197;           // 16 x 196
  float* Qb = Qa + 16*N_;            // 16 x 196

  const int t   = blockIdx.x;
  const int b   = blockIdx.y;
  const int tid = threadIdx.x;
  const int ty  = tid / 14, tx = tid % 14;
  const int r0  = ty * 7,   c0 = tx * 14;

  const float* qa_base = g_qA + (size_t)((b*T_ + t    )*N_) * D_;
  const float* qb_base = g_qA + (size_t)((b*T_ + t + 1)*N_) * D_;

  float acc[7][14];
#pragma unroll
  for (int i = 0; i < 7; ++i)
#pragma unroll
    for (int j = 0; j < 14; ++j) acc[i][j] = 0.f;

  for (int k0 = 0; k0 < D_; k0 += 16) {
    __syncthreads();
    for (int idx = tid; idx < N_*16; idx += 392) {
      const int n = idx >> 4, k = idx & 15;
      Qa[k*N_ + n] = qa_base[(size_t)n*D_ + k0 + k];
      Qb[k*N_ + n] = qb_base[(size_t)n*D_ + k0 + k];
    }
    __syncthreads();
#pragma unroll
    for (int k = 0; k < 16; ++k) {
      float ra[7], rb[14];
#pragma unroll
      for (int i = 0; i < 7; ++i)  ra[i] = Qa[k*N_ + r0 + i];
#pragma unroll
      for (int j = 0; j < 14; ++j) rb[j] = Qb[k*N_ + c0 + j];
#pragma unroll
      for (int i = 0; i < 7; ++i)
#pragma unroll
        for (int j = 0; j < 14; ++j) acc[i][j] += ra[i] * rb[j];
    }
  }
  __syncthreads();

#pragma unroll
  for (int i = 0; i < 7; ++i)
#pragma unroll
    for (int j = 0; j < 14; ++j)
      Sm[(r0 + i)*197 + (c0 + j)] = acc[i][j] * INV_TEMP;
  __syncthreads();

  for (int idx = tid; idx < N_*N_; idx += 392) {
    const int rr = idx / N_, mm = idx - rr*N_;
    Sm[rr*197 + mm] = __expf(Sm[rr*197 + mm]);
  }
  __syncthreads();

  float* rinv = Qa;
  float* cinv = Qa + N_;
  if (tid < N_) {
    float rs = 0.f, cs = 0.f;
    for (int m = 0; m < N_; ++m) {
      rs += Sm[tid*197 + m];
      cs += Sm[m*197 + tid];
    }
    rinv[tid] = 1.0f / rs;
    cinv[tid] = 1.0f / cs;
  }
  __syncthreads();

  float* Pf = g_P + (size_t)(b*S_ + t       )*MMP_;
  float* Pb = g_P + (size_t)(b*S_ + (37 - t))*MMP_;
  for (int idx = tid; idx < MMP_; idx += 392) {
    const int rr = idx / NP_, mm = idx - rr*NP_;
    float vf = 0.f, vb = 0.f;
    if (mm < N_) {
      vf = Sm[rr*197 + mm] * rinv[rr];
      vb = Sm[mm*197 + rr] * cinv[rr];
    }
    Pf[idx] = vf;
    Pb[idx] = vb;
  }
}

// =============================================================================
// Kernel C v2: product-tree GEMM, occupancy-optimized.
// C = src[2p+1] @ src[2p], M=196 (rows), N=224 (padded cols), K=196.
// CTA: 49 rows x 224 cols, 224 threads (7 warps). Thread tile 7x7.
// ty = warp id (row group, A reads broadcast), tx = lane (col group, stride-7
// B reads, 7 coprime 32 -> conflict-free). K chunk 28 (7 chunks).
// Epilogue staged through smem in two row batches for coalesced stores.
// =============================================================================
#define KC_ 28
#define SMEM_C_FLOATS (KC_*49 + KC_*NP_)     // As 1372 + Bs 6272 = 7644
#define SMEM_C_BYTES  (SMEM_C_FLOATS * sizeof(float))

__global__ __launch_bounds__(224, 3) void kC(int level, int Lin, int Lout, int npairs) {
  extern __shared__ float sm[];
  float* As = sm;                 // [k][i] KC_ x 49
  float* Bs = sm + KC_*49;        // [k][j] KC_ x 224

  const float* src; float* dst;
  switch (level) {
    case 0:  src = g_P;    dst = g_buf1; break;
    case 1:  src = g_buf1; dst = g_buf2; break;
    case 2:  src = g_buf2; dst = g_buf1; break;
    case 3:  src = g_buf1; dst = g_buf2; break;
    case 4:  src = g_buf2; dst = g_buf1; break;
    default: src = g_buf1; dst = g_buf2; break;
  }

  const int tile = blockIdx.x;        // 0..3 row tiles of 49
  const int p    = blockIdx.y;
  const int b    = blockIdx.z;
  const int tid  = threadIdx.x;

  if (p >= npairs) {                  // carry: copy last src matrix through
    const float4* Sg = reinterpret_cast<const float4*>(src + ((size_t)b*Lin + (Lin - 1))*MMP_);
    float4*       Dg = reinterpret_cast<float4*>(dst + ((size_t)b*Lout + npairs)*MMP_);
    const int q = MMP_/16;            // 2744 float4 per tile
    for (int i = tile*q + tid; i < (tile + 1)*q; i += 224) Dg[i] = Sg[i];
    return;
  }

  const float* Am = src + ((size_t)b*Lin + 2*p + 1)*MMP_;
  const float* Bm = src + ((size_t)b*Lin + 2*p    )*MMP_;
  float*       Cm = dst + ((size_t)b*Lout + p     )*MMP_;

  const int row0 = tile * 49;
  const int tx = tid & 31;            // lane -> col group
  const int ty = tid >> 5;            // warp -> row group
  const int r0 = ty * 7, c0 = tx * 7;

  float acc[7][7];
#pragma unroll
  for (int i = 0; i < 7; ++i)
#pragma unroll
    for (int j = 0; j < 7; ++j) acc[i][j] = 0.f;

  for (int k0 = 0; k0 < N_; k0 += KC_) {
    __syncthreads();
    // A chunk: 49 rows x 28 k, transposed into As[k][i]. 7 float4 per row.
    {
      const float4* A4 = reinterpret_cast<const float4*>(Am + (size_t)row0*NP_ + k0);
      for (int idx = tid; idx < 49*7; idx += 224) {
        const int i = idx / 7, c = idx - i*7;
        float4 v = A4[i*(NP_/4) + c];
        As[(4*c + 0)*49 + i] = v.x;
        As[(4*c + 1)*49 + i] = v.y;
        As[(4*c + 2)*49 + i] = v.z;
        As[(4*c + 3)*49 + i] = v.w;
      }
    }
    // B chunk: rows k0..k0+27, full padded width -> contiguous block copy.
    {
      const float4* B4  = reinterpret_cast<const float4*>(Bm + (size_t)k0*NP_);
      float4*       Bs4 = reinterpret_cast<float4*>(Bs);
      for (int idx = tid; idx < KC_*NP_/4; idx += 224) Bs4[idx] = B4[idx];
    }
    __syncthreads();
#pragma unroll 7
    for (int k = 0; k < KC_; ++k) {
      float a[7], bb[7];
#pragma unroll
      for (int i = 0; i < 7; ++i) a[i]  = As[k*49 + r0 + i];
#pragma unroll
      for (int j = 0; j < 7; ++j) bb[j] = Bs[k*NP_ + c0 + j];
#pragma unroll
      for (int i = 0; i < 7; ++i)
#pragma unroll
        for (int j = 0; j < 7; ++j) acc[i][j] += a[i] * bb[j];
    }
  }

  // ---- epilogue: stage through smem (reuse As+Bs = 7644 floats) in 2 batches
  float* St = sm;
  __syncthreads();
  // batch 0: local rows 0..27 (ty 0..3)
  if (ty < 4) {
#pragma unroll
    for (int i = 0; i < 7; ++i)
#pragma unroll
      for (int j = 0; j < 7; ++j)
        St[(r0 + i)*NP_ + (c0 + j)] = acc[i][j];
  }
  __syncthreads();
  for (int r = 0; r < 28; ++r)
    Cm[(size_t)(row0 + r)*NP_ + tid] = St[r*NP_ + tid];
  __syncthreads();
  // batch 1: local rows 28..48 (ty 4..6)
  if (ty >= 4) {
#pragma unroll
    for (int i = 0; i < 7; ++i)
#pragma unroll
      for (int j = 0; j < 7; ++j)
        St[(r0 - 28 + i)*NP_ + (c0 + j)] = acc[i][j];
  }
  __syncthreads();
  for (int r = 0; r < 21; ++r)
    Cm[(size_t)(row0 + 28 + r)*NP_ + tid] = St[r*NP_ + tid];
}

// =============================================================================
// Kernel D: per-row loss/acc from final At (g_buf2[b][0], padded stride).
// =============================================================================
__global__ void kD() {
  __shared__ float sl[N_], sa[N_];
  const int b = blockIdx.x, n = threadIdx.x;
  const float* row = g_buf2 + (size_t)b*MMP_ + (size_t)n*NP_;
  float rs = 0.f, best = -1.f;
  int bi = 0;
  for (int m = 0; m < N_; ++m) {
    const float v = row[m];
    rs += v;
    if (v > best) { best = v; bi = m; }
  }
  const float diag = row[n];
  sl[n] = logf(rs + (float)N_ * EPS_) - logf(diag + EPS_);
  sa[n] = (bi == n) ? 1.f : 0.f;
  __syncthreads();
  if (n == 0) {
    float L = 0.f, A = 0.f;
    for (int i = 0; i < N_; ++i) { L += sl[i]; A += sa[i]; }
    g_partial[b]      = L;
    g_partial[B_ + b] = A;
  }
}

__global__ void kE(float* out, int out_size) {
  float L = 0.f, A = 0.f;
  for (int b = 0; b < B_; ++b) { L += g_partial[b]; A += g_partial[B_ + b]; }
  const float inv = 1.0f / (float)(B_ * N_);
  if (out_size > QSIZE)     out[QSIZE]     = L * inv;
  if (out_size > QSIZE + 1) out[QSIZE + 1] = A * inv;
}

// =============================================================================
extern "C" void kernel_launch(void* const* d_in, const int* in_sizes, int n_in,
                              void* d_out, int out_size) {
  const float* maps = (const float*)d_in[0];
  const float* W    = (const float*)d_in[1];
  const float* bias = (const float*)d_in[2];
  float* out = (float*)d_out;

  cudaFuncSetAttribute(kA, cudaFuncAttributeMaxDynamicSharedMemorySize, (int)SMEM_A_BYTES);
  cudaFuncSetAttribute(kB, cudaFuncAttributeMaxDynamicSharedMemorySize, (int)SMEM_B_BYTES);
  cudaFuncSetAttribute(kC, cudaFuncAttributeMaxDynamicSharedMemorySize, (int)SMEM_C_BYTES);

  kA<<<B_*N_, 128, SMEM_A_BYTES>>>(maps, W, bias, out);
  kB<<<dim3(T_ - 1, B_), 392, SMEM_B_BYTES>>>();

  // product tree: 38 -> 19 -> 10 -> 5 -> 3 -> 2 -> 1
  // {level, Lin, Lout, npairs, carry}
  const int lv[6][5] = {
    {0, 38, 19, 19, 0},
    {1, 19, 10,  9, 1},
    {2, 10,  5,  5, 0},
    {3,  5,  3,  2, 1},
    {4,  3,  2,  1, 1},
    {5,  2,  1,  1, 0},
  };
  for (int l = 0; l < 6; ++l) {
    kC<<<dim3(4, lv[l][3] + lv[l][4], B_), 224, SMEM_C_BYTES>>>(
        lv[l][0], lv[l][1], lv[l][2], lv[l][3]);
  }

  kD<<<B_, N_>>>();
  kE<<<1, 1>>>(out, out_size);
}